// round 17
// baseline (speedup 1.0000x reference)
#include <cuda_runtime.h>

#define SS 512
#define NUNITS 9
#define DSTRIDE 544   // row pitch 2176 B = 17 x 128B lines
#define MAXB 128
#define PLANE (MAXB * DSTRIDE)   // floats per shifted plane

// Three shift-staggered planes: g_diag[k*PLANE + b*DSTRIDE + j] = diag[b][j+4k]
// (zero beyond j+4k >= 512). Each of the kernel's three window loads is then
// a 512B line-aligned warp access: 4 wavefronts instead of 4+5+5.
__device__ __align__(256) float g_diag[3 * PLANE];
__device__ float g_bias[SS * SS];

// Fused prep: diag gather+replicate (low blocks); bias reduction (high blocks)
// via coalesced float4 -> smem -> conflict-free scalar reads (9t+i mod 32).
__global__ void prep_kernel(const float* __restrict__ in,
                            const float* __restrict__ bb,
                            int B, int ndiag_blocks) {
    __shared__ float sb[256 * 9];
    if (blockIdx.x < (unsigned)ndiag_blocks) {
        // j range extended to DSTRIDE+8 so shifted planes get their zero tails
        const int JR = DSTRIDE + 8;                  // 552
        int idx = blockIdx.x * blockDim.x + threadIdx.x;
        int bq = idx / JR;
        int j  = idx - bq * JR;
        int b4 = bq * 4;
        if (b4 >= B) return;
        float v[4] = {0.f, 0.f, 0.f, 0.f};
        bool jin = (j < SS);
#pragma unroll
        for (int k = 0; k < 4; k++) {
            if (jin && b4 + k < B)
                v[k] = __ldg(in + (size_t)(b4 + k) * SS * SS + (size_t)j * (SS + 1));
        }
#pragma unroll
        for (int k = 0; k < 4; k++) {
            if (b4 + k < B) {
                size_t row = (size_t)(b4 + k) * DSTRIDE;
                if (j < DSTRIDE)           g_diag[row + j] = v[k];
                if (j >= 4 && j - 4 < DSTRIDE) g_diag[PLANE + row + (j - 4)] = v[k];
                if (j >= 8 && j - 8 < DSTRIDE) g_diag[2 * PLANE + row + (j - 8)] = v[k];
            }
        }
    } else {
        int tid = threadIdx.x;
        int out0 = (blockIdx.x - ndiag_blocks) * 256;
        const float4* src = (const float4*)(bb + (size_t)out0 * 9);
        float4* s4 = (float4*)sb;
#pragma unroll
        for (int r = 0; r < 3; r++) {
            int k = tid + r * 256;
            if (k < 576) s4[k] = src[k];
        }
        __syncthreads();
        float acc = 0.0f;
#pragma unroll
        for (int t = 0; t < 9; t++) acc += sb[tid * 9 + t];
        g_bias[out0 + tid] = acc;
    }
}

// Main kernel (R13 shape): per iter 3x line-aligned LDG.128 (one per plane,
// 12 read-wf total) + 36 FMA + 1x STG.128. Rotation + PDL. 7 blocks/SM.
__global__ __launch_bounds__(128, 7)
void cnn_kernel(const float* __restrict__ w,
                float* __restrict__ out,
                int B, int bper) {
    int i  = blockIdx.x;          // 0..511
    int j0 = threadIdx.x << 2;    // 0,4,...,508
    int b0 = blockIdx.y * bper;
    int b1 = b0 + bper;
    if (b1 > B) b1 = B;
    if (b0 >= b1) { cudaGridDependencySynchronize(); return; }
    int nb = b1 - b0;

    // ---- prologue (independent of prep): 9x LDG.128 weights ----
    float wv[36];
    const float4* wp4 = (const float4*)(w + ((size_t)i * SS + j0) * NUNITS);
#pragma unroll
    for (int k = 0; k < 9; k++) {
        float4 q = wp4[k];
        wv[k * 4 + 0] = q.x; wv[k * 4 + 1] = q.y;
        wv[k * 4 + 2] = q.z; wv[k * 4 + 3] = q.w;
    }
#pragma unroll
    for (int n = 0; n < 36; n++) {
        int t = n % 9;                          // compile-time per n
        wv[n] *= (i + (t / 3) < SS) ? 9.0f : 0.0f;
    }

    // ---- wait for prep results ----
    cudaGridDependencySynchronize();

    float4 bias4 = *(const float4*)(g_bias + (size_t)i * SS + j0);

    const float* dbase = g_diag + (size_t)b0 * DSTRIDE + j0;
    float* obase = out + (size_t)b0 * (SS * SS) + (size_t)i * SS + j0;

    // rotation phase: decorrelate rows across blocks
    int idx = (blockIdx.x * 7) % nb;

    for (int lb = 0; lb < nb; ++lb) {
        const float* drow = dbase + (size_t)idx * DSTRIDE;
        float4 c0 = *(const float4*)drow;                 // plane 0: d[0..3]
        float4 c1 = *(const float4*)(drow + PLANE);       // plane 1: d[4..7]
        float4 c2 = *(const float4*)(drow + 2 * PLANE);   // plane 2: d[8..11]
        float d[12] = {c0.x, c0.y, c0.z, c0.w,
                       c1.x, c1.y, c1.z, c1.w,
                       c2.x, c2.y, c2.z, c2.w};

        float s0 = bias4.x, s1 = bias4.y, s2 = bias4.z, s3 = bias4.w;
#pragma unroll
        for (int t = 0; t < 9; t++) {
            s0 = fmaf(d[t],     wv[t],      s0);
            s1 = fmaf(d[t + 1], wv[9 + t],  s1);
            s2 = fmaf(d[t + 2], wv[18 + t], s2);
            s3 = fmaf(d[t + 3], wv[27 + t], s3);
        }
        float4 o; o.x = s0; o.y = s1; o.z = s2; o.w = s3;
        __stcs((float4*)(obase + (size_t)idx * (SS * SS)), o);

        ++idx;
        idx = (idx == nb) ? 0 : idx;            // branch-free wrap
    }
}

extern "C" void kernel_launch(void* const* d_in, const int* in_sizes, int n_in,
                              void* d_out, int out_size) {
    const float* in = (const float*)d_in[0];   // inputs (B,512,512,1) f32
    const float* w  = (const float*)d_in[1];   // w (512*512*9,) f32
    const float* bb = (const float*)d_in[2];   // b (512*512*9,) f32
    float* out = (float*)d_out;                // (B, 512*512) f32

    int B = in_sizes[0] / (SS * SS);
    if (B > MAXB) B = MAXB;

    {
        int bq = (B + 3) / 4;
        int ndiag_blocks = (bq * (DSTRIDE + 8) + 255) / 256;  // ~54
        int nbias_blocks = (SS * SS) / 256;                   // 1024
        prep_kernel<<<ndiag_blocks + nbias_blocks, 256>>>(in, bb, B, ndiag_blocks);
    }

    const int NSLICE = 6;                      // 3072 blocks ~= 2.97 waves @ 7/SM
    int bper = (B + NSLICE - 1) / NSLICE;      // 17
    dim3 grid(SS, NSLICE);

    cudaLaunchConfig_t cfg = {};
    cfg.gridDim = grid;
    cfg.blockDim = dim3(128, 1, 1);
    cfg.dynamicSmemBytes = 0;
    cfg.stream = 0;
    cudaLaunchAttribute attrs[1];
    attrs[0].id = cudaLaunchAttributeProgrammaticStreamSerialization;
    attrs[0].val.programmaticStreamSerializationAllowed = 1;
    cfg.attrs = attrs;
    cfg.numAttrs = 1;
    cudaError_t e = cudaLaunchKernelEx(&cfg, cnn_kernel, w, out, B, bper);
    if (e != cudaSuccess) {
        cnn_kernel<<<grid, 128>>>(w, out, B, bper);
    }
}